// round 16
// baseline (speedup 1.0000x reference)
#include <cuda_runtime.h>
#include <cuda_fp16.h>
#include <math.h>

// Problem constants
#define NWIN 32
#define NH   8
#define LW   784
#define HD   32
#define CDIM 256
#define TTOK 25088
#define SCALE_LOG2E 0.25500299929874094f     // 32^-0.5 * log2(e)

// Scratch (all fp16)
__device__ __half g_qh[(size_t)NWIN * NH * LW * HD];   // pre-scaled fp16 Q
__device__ __half g_kh[(size_t)NWIN * NH * LW * HD];   // fp16 K
__device__ __half g_vt[(size_t)NWIN * NH * HD * LW];   // transposed fp16 V
__device__ __half g_xf[(size_t)TTOK * CDIM];           // fp16 input x
__device__ __half g_wqf[768 * CDIM];                   // fp16 qkv weight
__device__ __half g_wpf[CDIM * CDIM];                  // fp16 proj weight
__device__ __half g_of[(size_t)TTOK * CDIM];           // fp16 attention out

#define ONES_H2 0x3C003C00u   // half2(1.0, 1.0)

// ---------------------------------------------------------------------------
// helpers
// ---------------------------------------------------------------------------
__device__ __forceinline__ float ex2f(float x)
{
    float y;
    asm("ex2.approx.f32 %0, %1;" : "=f"(y) : "f"(x));
    return y;
}

__device__ __forceinline__ void mma_f16(
    float d[4], unsigned a0, unsigned a1, unsigned a2, unsigned a3,
    unsigned b0, unsigned b1)
{
    asm volatile(
        "mma.sync.aligned.m16n8k16.row.col.f32.f16.f16.f32 "
        "{%0,%1,%2,%3},{%4,%5,%6,%7},{%8,%9},{%0,%1,%2,%3};"
        : "+f"(d[0]), "+f"(d[1]), "+f"(d[2]), "+f"(d[3])
        : "r"(a0), "r"(a1), "r"(a2), "r"(a3), "r"(b0), "r"(b1));
}

__device__ __forceinline__ void ldsm_x4(
    unsigned& r0, unsigned& r1, unsigned& r2, unsigned& r3, const void* p)
{
    unsigned a = (unsigned)__cvta_generic_to_shared(p);
    asm volatile("ldmatrix.sync.aligned.m8n8.x4.shared.b16 {%0,%1,%2,%3}, [%4];"
                 : "=r"(r0), "=r"(r1), "=r"(r2), "=r"(r3) : "r"(a));
}

__device__ __forceinline__ void ldsm_x2(
    unsigned& r0, unsigned& r1, const void* p)
{
    unsigned a = (unsigned)__cvta_generic_to_shared(p);
    asm volatile("ldmatrix.sync.aligned.m8n8.x2.shared.b16 {%0,%1}, [%2];"
                 : "=r"(r0), "=r"(r1) : "r"(a));
}

#define CP16(dst_u32, src_ptr) \
    asm volatile("cp.async.cg.shared.global [%0], [%1], 16;" \
                 :: "r"(dst_u32), "l"(src_ptr))

// ---------------------------------------------------------------------------
// Kernel 0: fp32 -> fp16 convert (x, qkv_w, proj_w in ONE launch).
// ---------------------------------------------------------------------------
#define XB  ((TTOK * CDIM) / 1024)   // 6272 blocks
#define WQB ((768 * CDIM) / 1024)    // 192 blocks
#define WPB ((CDIM * CDIM) / 1024)   // 64 blocks

__global__ __launch_bounds__(256) void conv_all_kernel(
    const float* __restrict__ x, const float* __restrict__ wq,
    const float* __restrict__ wp)
{
    int b = blockIdx.x;
    const float* src;
    __half* dst;
    if (b < XB)            { src = x;  dst = g_xf; }
    else if (b < XB + WQB) { src = wq; dst = g_wqf; b -= XB; }
    else                   { src = wp; dst = g_wpf; b -= XB + WQB; }
    size_t i4 = ((size_t)b * 256 + threadIdx.x) * 4;
    float4 v = *(const float4*)&src[i4];
    __half2 a = __floats2half2_rn(v.x, v.y);
    __half2 c = __floats2half2_rn(v.z, v.w);
    *(unsigned*)&dst[i4]     = *(unsigned*)&a;
    *(unsigned*)&dst[i4 + 2] = *(unsigned*)&c;
}

// ---------------------------------------------------------------------------
// Plain-fp16 tensor-core GEMM (128x128 tile, 8 warps of 64x32),
// 3-stage cp.async pipeline, ldmatrix fragment loads.
// ---------------------------------------------------------------------------
#define BK 32
#define SRS 40   // smem row stride in halves (80 B rows, conflict-free ldsm)

struct GemmSmem {
    __half A[128 * SRS];
    __half B[128 * SRS];
};
#define GEMM_SMEM_BYTES (3 * (int)sizeof(GemmSmem))

__device__ __forceinline__ void gemm_issue(
    const __half* __restrict__ GA, const __half* __restrict__ GB,
    GemmSmem* S, size_t rowA, size_t rowB, int k0, int tid)
{
#pragma unroll
    for (int j = 0; j < 2; j++) {
        int idx = tid + j * 256;
        int r = idx >> 2;
        int c8 = (idx & 3) << 3;
        CP16((unsigned)__cvta_generic_to_shared(&S->A[r * SRS + c8]),
             &GA[(rowA + r) * CDIM + k0 + c8]);
        CP16((unsigned)__cvta_generic_to_shared(&S->B[r * SRS + c8]),
             &GB[(rowB + r) * CDIM + k0 + c8]);
    }
}

__device__ __forceinline__ void mma_chunk(
    const GemmSmem* S, int wm, int wn, int lane, float acc[4][4][4])
{
    const int lrow = lane & 15;
    const int lko  = ((lane >> 4) & 1) * 8;
    const int g    = lane >> 3;
    const int bnr  = ((g >> 1) & 1) * 8 + (lane & 7);
    const int bko  = (g & 1) * 8;

#pragma unroll
    for (int ks = 0; ks < 2; ks++) {
        const int kb = ks * 16;
        unsigned ar[4][4], br[4][2];
#pragma unroll
        for (int mf = 0; mf < 4; mf++) {
            int off = (wm * 64 + mf * 16 + lrow) * SRS + kb + lko;
            ldsm_x4(ar[mf][0], ar[mf][1], ar[mf][2], ar[mf][3], &S->A[off]);
        }
#pragma unroll
        for (int nfp = 0; nfp < 2; nfp++) {
            int off = (wn * 32 + nfp * 16 + bnr) * SRS + kb + bko;
            ldsm_x4(br[2 * nfp][0], br[2 * nfp][1],
                    br[2 * nfp + 1][0], br[2 * nfp + 1][1], &S->B[off]);
        }
#pragma unroll
        for (int mf = 0; mf < 4; mf++)
#pragma unroll
            for (int nf = 0; nf < 4; nf++)
                mma_f16(acc[mf][nf], ar[mf][0], ar[mf][1], ar[mf][2], ar[mf][3],
                        br[nf][0], br[nf][1]);
    }
}

__device__ __forceinline__ void gemm_mainloop(
    const __half* __restrict__ GA, const __half* __restrict__ GB,
    GemmSmem* SS, size_t t0, size_t o0, int tid,
    int wm, int wn, int lane, float acc[4][4][4])
{
    gemm_issue(GA, GB, &SS[0], t0, o0, 0, tid);
    asm volatile("cp.async.commit_group;" ::: "memory");
    gemm_issue(GA, GB, &SS[1], t0, o0, BK, tid);
    asm volatile("cp.async.commit_group;" ::: "memory");

#pragma unroll
    for (int kc = 0; kc < 8; kc++) {
        if (kc < 7)
            asm volatile("cp.async.wait_group 1;" ::: "memory");
        else
            asm volatile("cp.async.wait_group 0;" ::: "memory");
        __syncthreads();
        if (kc < 6) {
            gemm_issue(GA, GB, &SS[(kc + 2) % 3], t0, o0, (kc + 2) * BK, tid);
            asm volatile("cp.async.commit_group;" ::: "memory");
        }
        mma_chunk(&SS[kc % 3], wm, wn, lane, acc);
    }
}

// ---------------------------------------------------------------------------
// Kernel 1: QKV projection (fp16). Epilogue: Q fp16 pre-scaled, K fp16,
// V transposed fp16.
// ---------------------------------------------------------------------------
__global__ __launch_bounds__(256, 2) void qkv_gemm_kernel()
{
    extern __shared__ GemmSmem SS[];

    const int tid  = threadIdx.x;
    const int lane = tid & 31;
    const int warp = tid >> 5;
    const int gid  = lane >> 2;
    const int tig  = lane & 3;
    const int wm   = warp & 1;
    const int wn   = warp >> 1;
    const int t0   = blockIdx.x * 128;
    const int o0   = blockIdx.y * 128;

    float acc[4][4][4];
#pragma unroll
    for (int mf = 0; mf < 4; mf++)
#pragma unroll
        for (int nf = 0; nf < 4; nf++)
#pragma unroll
            for (int i = 0; i < 4; i++) acc[mf][nf][i] = 0.f;

    gemm_mainloop(g_xf, g_wqf, SS, t0, o0, tid, wm, wn, lane, acc);

    const int ocol0 = o0 + wn * 32;
    const int sel = ocol0 >> 8;
    const int h   = (ocol0 >> 5) & 7;

    if (sel < 2) {
        __half* dst = (sel == 0) ? g_qh : g_kh;
        float s = (sel == 0) ? SCALE_LOG2E : 1.f;
#pragma unroll
        for (int mf = 0; mf < 4; mf++) {
#pragma unroll
            for (int half = 0; half < 2; half++) {
                int t = t0 + wm * 64 + mf * 16 + gid + half * 8;
                int w = t / LW;
                int l = t - w * LW;
                size_t base = (size_t)((w * NH + h) * LW + l) * HD;
#pragma unroll
                for (int nf = 0; nf < 4; nf++) {
                    int d = nf * 8 + 2 * tig;
                    __half2 hv = __floats2half2_rn(
                        acc[mf][nf][half * 2] * s,
                        acc[mf][nf][half * 2 + 1] * s);
                    *(unsigned*)&dst[base + d] = *(unsigned*)&hv;
                }
            }
        }
    } else {
        // V: transposed fp16 store g_vt[(w*NH+h)*HD + d][l]
#pragma unroll
        for (int mf = 0; mf < 4; mf++) {
#pragma unroll
            for (int half = 0; half < 2; half++) {
                int t = t0 + wm * 64 + mf * 16 + gid + half * 8;
                int w = t / LW;
                int l = t - w * LW;
                size_t vb = (size_t)((w * NH + h) * HD) * LW + l;
#pragma unroll
                for (int nf = 0; nf < 4; nf++) {
                    int d = nf * 8 + 2 * tig;
                    g_vt[vb + (size_t)d * LW] =
                        __float2half_rn(acc[mf][nf][half * 2]);
                    g_vt[vb + (size_t)(d + 1) * LW] =
                        __float2half_rn(acc[mf][nf][half * 2 + 1]);
                }
            }
        }
    }
}

// ---------------------------------------------------------------------------
// Kernel 2: flash attention, all-fp16 mma, 3-stage cp.async pipeline,
// hoisted Q frags, ldmatrix K/V frags, MUFU softmax + ones-mma row sums.
// grid = (7, 256), block = 224 (7 warps), 3 CTAs/SM.
// ---------------------------------------------------------------------------
#define QKS 40
#define VTS 120
#define Q_HALVES  (112 * QKS)
#define K_HALVES  (112 * QKS)
#define V_HALVES  (HD * VTS)
#define ATTN_SMEM_BYTES ((Q_HALVES + 3 * K_HALVES + 3 * V_HALVES) * 2)

template<int NGN, int NGBASE>
__device__ __forceinline__ void attn_part(
    const unsigned qf[2][4], const __half* __restrict__ Ks,
    const __half* __restrict__ Vs, int lane,
    float oacc[4][4], float lsum[4])
{
    const int bnr = ((lane >> 4) & 1) * 8 + (lane & 7);  // K ldsm row-in-16
    const int bko = ((lane >> 3) & 1) * 8;               // K ldsm k-offset
    const int vr  = lane & 7;                            // V ldsm row-in-8
    const int vko = ((lane >> 3) & 1) * 8;               // V ldsm k-offset

    float sacc[NGN][4];
#pragma unroll
    for (int ngl = 0; ngl < NGN; ngl++)
#pragma unroll
        for (int i = 0; i < 4; i++) sacc[ngl][i] = 0.f;

    // S = Q K^T ; K fragments via ldmatrix.x4 (ngl pair per load)
#pragma unroll
    for (int p = 0; p < NGN / 2; p++) {
#pragma unroll
        for (int ks = 0; ks < 2; ks++) {
            const __half* kb =
                &Ks[((NGBASE + 2 * p) * 8 + bnr) * QKS + ks * 16 + bko];
            unsigned b0, b1, b2, b3;
            ldsm_x4(b0, b1, b2, b3, kb);
            mma_f16(sacc[2 * p],     qf[ks][0], qf[ks][1], qf[ks][2],
                    qf[ks][3], b0, b1);
            mma_f16(sacc[2 * p + 1], qf[ks][0], qf[ks][1], qf[ks][2],
                    qf[ks][3], b2, b3);
        }
    }

    // exp (MUFU) -> fp16 pack -> PV mma (V frags via ldmatrix.x2) + ones-mma
#pragma unroll
    for (int ch = 0; ch < NGN / 2; ch++) {
        int ngl0 = 2 * ch, ngl1 = 2 * ch + 1;
        __half2 h0 = __floats2half2_rn(ex2f(sacc[ngl0][0]),
                                       ex2f(sacc[ngl0][1]));
        __half2 h1 = __floats2half2_rn(ex2f(sacc[ngl0][2]),
                                       ex2f(sacc[ngl0][3]));
        __half2 h2 = __floats2half2_rn(ex2f(sacc[ngl1][0]),
                                       ex2f(sacc[ngl1][1]));
        __half2 h3 = __floats2half2_rn(ex2f(sacc[ngl1][2]),
                                       ex2f(sacc[ngl1][3]));
        unsigned a0 = *(unsigned*)&h0, a1 = *(unsigned*)&h1;
        unsigned a2 = *(unsigned*)&h2, a3 = *(unsigned*)&h3;
        int kbase = (NGBASE / 2 + ch) * 16;
#pragma unroll
        for (int ng = 0; ng < 4; ng++) {
            const __half* vb = &Vs[(ng * 8 + vr) * VTS + kbase + vko];
            unsigned b0, b1;
            ldsm_x2(b0, b1, vb);
            mma_f16(oacc[ng], a0, a1, a2, a3, b0, b1);
        }
        mma_f16(lsum, a0, a1, a2, a3, ONES_H2, ONES_H2);
    }
}

__device__ __forceinline__ void attn_issue_tile(
    __half* Kd, __half* Vd, const __half* gkt, const __half* gvtt, int tid)
{
#pragma unroll
    for (int i2 = 0; i2 < 2; i2++) {
        int i = tid + i2 * 224;
        int r = i >> 2;
        int c = (i & 3) << 3;
        CP16((unsigned)__cvta_generic_to_shared(&Kd[r * QKS + c]),
             &gkt[r * 32 + c]);
    }
#pragma unroll
    for (int i2 = 0; i2 < 2; i2++) {
        int i = tid + i2 * 224;
        int d = i / 14;
        int c = i - d * 14;
        CP16((unsigned)__cvta_generic_to_shared(&Vd[d * VTS + c * 8]),
             &gvtt[(size_t)d * LW + c * 8]);
    }
    asm volatile("cp.async.commit_group;" ::: "memory");
}

__global__ __launch_bounds__(224, 3) void attn_kernel()
{
    extern __shared__ char smraw[];
    __half* Qs  = (__half*)smraw;                 // [112][40]
    __half* Ks0 = Qs + Q_HALVES;                  // 3 x [112][40]
    __half* Vs0 = Ks0 + 3 * K_HALVES;             // 3 x [32][120]

    const int tid  = threadIdx.x;
    const int lane = tid & 31;
    const int warp = tid >> 5;
    const int gid  = lane >> 2;
    const int tig  = lane & 3;
    const int m0   = warp * 16;

    const int wh = blockIdx.y;
    const int q0 = blockIdx.x * 112;

    const __half* gq  = g_qh + (size_t)(wh * LW + q0) * HD;
    const __half* gk  = g_kh + (size_t)wh * LW * HD;
    const __half* gvt = g_vt + (size_t)wh * HD * LW;

    // group 0: Q + K/V tile 0
    {
#pragma unroll
        for (int i2 = 0; i2 < 2; i2++) {
            int i = tid + i2 * 224;
            int r = i >> 2;
            int c = (i & 3) << 3;
            CP16((unsigned)__cvta_generic_to_shared(&Qs[r * QKS + c]),
                 &gq[r * 32 + c]);
            CP16((unsigned)__cvta_generic_to_shared(&Ks0[r * QKS + c]),
                 &gk[r * 32 + c]);
        }
#pragma unroll
        for (int i2 = 0; i2 < 2; i2++) {
            int i = tid + i2 * 224;
            int d = i / 14;
            int c = i - d * 14;
            CP16((unsigned)__cvta_generic_to_shared(&Vs0[d * VTS + c * 8]),
                 &gvt[(size_t)d * LW + c * 8]);
        }
        asm volatile("cp.async.commit_group;" ::: "memory");
    }
    // group 1: K/V tile 1
    attn_issue_tile(Ks0 + K_HALVES, Vs0 + V_HALVES,
                    gk + 112 * 32, gvt + 112, tid);

    float oacc[4][4];
#pragma unroll
    for (int ng = 0; ng < 4; ng++)
#pragma unroll
        for (int i = 0; i < 4; i++) oacc[ng][i] = 0.f;
    float lsum[4] = {0.f, 0.f, 0.f, 0.f};
    unsigned qf[2][4];

    for (int kt = 0; kt < 7; kt++) {
        if (kt < 6)
            asm volatile("cp.async.wait_group 1;" ::: "memory");
        else
            asm volatile("cp.async.wait_group 0;" ::: "memory");
        __syncthreads();
        if (kt == 0) {
            // hoist Q fragments (kt-invariant)
#pragma unroll
            for (int ks = 0; ks < 2; ks++) {
                const __half* qb = &Qs[(m0 + gid) * QKS + ks * 16 + 2 * tig];
                qf[ks][0] = *(const unsigned*)qb;
                qf[ks][1] = *(const unsigned*)(qb + 8 * QKS);
                qf[ks][2] = *(const unsigned*)(qb + 8);
                qf[ks][3] = *(const unsigned*)(qb + 8 * QKS + 8);
            }
        }
        if (kt < 5) {
            attn_issue_tile(Ks0 + ((kt + 2) % 3) * K_HALVES,
                            Vs0 + ((kt + 2) % 3) * V_HALVES,
                            gk + (kt + 2) * 112 * 32,
                            gvt + (kt + 2) * 112, tid);
        }

        const __half* Ks = Ks0 + (kt % 3) * K_HALVES;
        const __half* Vs = Vs0 + (kt % 3) * V_HALVES;

        attn_part<8, 0>(qf, Ks, Vs, lane, oacc, lsum);
        attn_part<6, 8>(qf, Ks, Vs, lane, oacc, lsum);
    }

    float inv0 = 1.f / lsum[0];
    float inv1 = 1.f / lsum[2];

    // write O as fp16 for the proj GEMM
    const int w = wh >> 3;
    const int h = wh & 7;
    const size_t tbase = (size_t)(w * LW + q0 + m0 + gid);
#pragma unroll
    for (int ng = 0; ng < 4; ng++) {
        int col = h * HD + ng * 8 + 2 * tig;
        __half2 hv0 = __floats2half2_rn(oacc[ng][0] * inv0,
                                        oacc[ng][1] * inv0);
        __half2 hv1 = __floats2half2_rn(oacc[ng][2] * inv1,
                                        oacc[ng][3] * inv1);
        *(unsigned*)&g_of[tbase * CDIM + col]       = *(unsigned*)&hv0;
        *(unsigned*)&g_of[(tbase + 8) * CDIM + col] = *(unsigned*)&hv1;
    }
}

// ---------------------------------------------------------------------------
// Kernel 3: output projection (fp16) + bias.
// ---------------------------------------------------------------------------
__global__ __launch_bounds__(256, 2) void proj_gemm_kernel(
    const float* __restrict__ bias, float* __restrict__ out)
{
    extern __shared__ GemmSmem SS[];

    const int tid  = threadIdx.x;
    const int lane = tid & 31;
    const int warp = tid >> 5;
    const int gid  = lane >> 2;
    const int tig  = lane & 3;
    const int wm   = warp & 1;
    const int wn   = warp >> 1;
    const int t0   = blockIdx.x * 128;
    const int o0   = blockIdx.y * 128;

    float acc[4][4][4];
#pragma unroll
    for (int mf = 0; mf < 4; mf++)
#pragma unroll
        for (int nf = 0; nf < 4; nf++)
#pragma unroll
            for (int i = 0; i < 4; i++) acc[mf][nf][i] = 0.f;

    gemm_mainloop(g_of, g_wpf, SS, t0, o0, tid, wm, wn, lane, acc);

    const int ocol0 = o0 + wn * 32;
#pragma unroll
    for (int mf = 0; mf < 4; mf++) {
#pragma unroll
        for (int half = 0; half < 2; half++) {
            int t = t0 + wm * 64 + mf * 16 + gid + half * 8;
#pragma unroll
            for (int nf = 0; nf < 4; nf++) {
                int o = ocol0 + nf * 8 + 2 * tig;
                float2 bv = *(const float2*)&bias[o];
                *(float2*)&out[(size_t)t * CDIM + o] = make_float2(
                    acc[mf][nf][half * 2] + bv.x,
                    acc[mf][nf][half * 2 + 1] + bv.y);
            }
        }
    }
}

// ---------------------------------------------------------------------------
extern "C" void kernel_launch(void* const* d_in, const int* in_sizes, int n_in,
                              void* d_out, int out_size)
{
    const float* x      = (const float*)d_in[0];
    const float* qkv_w  = (const float*)d_in[1];
    const float* proj_w = (const float*)d_in[2];
    const float* proj_b = (const float*)d_in[3];
    float* out = (float*)d_out;

    cudaFuncSetAttribute(qkv_gemm_kernel,
                         cudaFuncAttributeMaxDynamicSharedMemorySize,
                         GEMM_SMEM_BYTES);
    cudaFuncSetAttribute(proj_gemm_kernel,
                         cudaFuncAttributeMaxDynamicSharedMemorySize,
                         GEMM_SMEM_BYTES);
    cudaFuncSetAttribute(attn_kernel,
                         cudaFuncAttributeMaxDynamicSharedMemorySize,
                         ATTN_SMEM_BYTES);

    conv_all_kernel<<<XB + WQB + WPB, 256>>>(x, qkv_w, proj_w);
    qkv_gemm_kernel<<<dim3(TTOK / 128, 768 / 128), 256, GEMM_SMEM_BYTES>>>();
    attn_kernel<<<dim3(LW / 112, NWIN * NH), 224, ATTN_SMEM_BYTES>>>();
    proj_gemm_kernel<<<dim3(TTOK / 128, CDIM / 128), 256, GEMM_SMEM_BYTES>>>(proj_b, out);
}

// round 17
// speedup vs baseline: 1.0916x; 1.0916x over previous
#include <cuda_runtime.h>
#include <cuda_fp16.h>
#include <math.h>

// Problem constants
#define NWIN 32
#define NH   8
#define LW   784
#define HD   32
#define CDIM 256
#define TTOK 25088
#define SCALE_LOG2E 0.25500299929874094f     // 32^-0.5 * log2(e)

// Scratch (all fp16)
__device__ __half g_qh[(size_t)NWIN * NH * LW * HD];   // pre-scaled fp16 Q
__device__ __half g_kh[(size_t)NWIN * NH * LW * HD];   // fp16 K
__device__ __half g_vt[(size_t)NWIN * NH * HD * LW];   // transposed fp16 V
__device__ __half g_xf[(size_t)TTOK * CDIM];           // fp16 input x
__device__ __half g_wqf[768 * CDIM];                   // fp16 qkv weight
__device__ __half g_wpf[CDIM * CDIM];                  // fp16 proj weight
__device__ __half g_of[(size_t)TTOK * CDIM];           // fp16 attention out

#define ONES_H2 0x3C003C00u   // half2(1.0, 1.0)

// ---------------------------------------------------------------------------
// helpers
// ---------------------------------------------------------------------------
__device__ __forceinline__ unsigned ex2_h2(__half2 x)
{
    unsigned y;
    asm("ex2.approx.f16x2 %0, %1;" : "=r"(y) : "r"(*(unsigned*)&x));
    return y;
}

__device__ __forceinline__ void mma_f16(
    float d[4], unsigned a0, unsigned a1, unsigned a2, unsigned a3,
    unsigned b0, unsigned b1)
{
    asm volatile(
        "mma.sync.aligned.m16n8k16.row.col.f32.f16.f16.f32 "
        "{%0,%1,%2,%3},{%4,%5,%6,%7},{%8,%9},{%0,%1,%2,%3};"
        : "+f"(d[0]), "+f"(d[1]), "+f"(d[2]), "+f"(d[3])
        : "r"(a0), "r"(a1), "r"(a2), "r"(a3), "r"(b0), "r"(b1));
}

__device__ __forceinline__ void ldsm_x4(
    unsigned& r0, unsigned& r1, unsigned& r2, unsigned& r3, const void* p)
{
    unsigned a = (unsigned)__cvta_generic_to_shared(p);
    asm volatile("ldmatrix.sync.aligned.m8n8.x4.shared.b16 {%0,%1,%2,%3}, [%4];"
                 : "=r"(r0), "=r"(r1), "=r"(r2), "=r"(r3) : "r"(a));
}

__device__ __forceinline__ void ldsm_x2(
    unsigned& r0, unsigned& r1, const void* p)
{
    unsigned a = (unsigned)__cvta_generic_to_shared(p);
    asm volatile("ldmatrix.sync.aligned.m8n8.x2.shared.b16 {%0,%1}, [%2];"
                 : "=r"(r0), "=r"(r1) : "r"(a));
}

#define CP16(dst_u32, src_ptr) \
    asm volatile("cp.async.cg.shared.global [%0], [%1], 16;" \
                 :: "r"(dst_u32), "l"(src_ptr))

// ---------------------------------------------------------------------------
// Kernel 0: fp32 -> fp16 convert (x, qkv_w, proj_w in ONE launch).
// ---------------------------------------------------------------------------
#define XB  ((TTOK * CDIM) / 1024)
#define WQB ((768 * CDIM) / 1024)
#define WPB ((CDIM * CDIM) / 1024)

__global__ __launch_bounds__(256) void conv_all_kernel(
    const float* __restrict__ x, const float* __restrict__ wq,
    const float* __restrict__ wp)
{
    int b = blockIdx.x;
    const float* src;
    __half* dst;
    if (b < XB)            { src = x;  dst = g_xf; }
    else if (b < XB + WQB) { src = wq; dst = g_wqf; b -= XB; }
    else                   { src = wp; dst = g_wpf; b -= XB + WQB; }
    size_t i4 = ((size_t)b * 256 + threadIdx.x) * 4;
    float4 v = *(const float4*)&src[i4];
    __half2 a = __floats2half2_rn(v.x, v.y);
    __half2 c = __floats2half2_rn(v.z, v.w);
    *(unsigned*)&dst[i4]     = *(unsigned*)&a;
    *(unsigned*)&dst[i4 + 2] = *(unsigned*)&c;
}

// ---------------------------------------------------------------------------
// Plain-fp16 tensor-core GEMM (128x128 tile, 8 warps of 64x32),
// 3-stage cp.async pipeline, ldmatrix fragment loads.
// ---------------------------------------------------------------------------
#define BK 32
#define SRS 40

struct GemmSmem {
    __half A[128 * SRS];
    __half B[128 * SRS];
};
#define GEMM_SMEM_BYTES (3 * (int)sizeof(GemmSmem))

__device__ __forceinline__ void gemm_issue(
    const __half* __restrict__ GA, const __half* __restrict__ GB,
    GemmSmem* S, size_t rowA, size_t rowB, int k0, int tid)
{
#pragma unroll
    for (int j = 0; j < 2; j++) {
        int idx = tid + j * 256;
        int r = idx >> 2;
        int c8 = (idx & 3) << 3;
        CP16((unsigned)__cvta_generic_to_shared(&S->A[r * SRS + c8]),
             &GA[(rowA + r) * CDIM + k0 + c8]);
        CP16((unsigned)__cvta_generic_to_shared(&S->B[r * SRS + c8]),
             &GB[(rowB + r) * CDIM + k0 + c8]);
    }
}

__device__ __forceinline__ void mma_chunk(
    const GemmSmem* S, int wm, int wn, int lane, float acc[4][4][4])
{
    const int lrow = lane & 15;
    const int lko  = ((lane >> 4) & 1) * 8;
    const int g    = lane >> 3;
    const int bnr  = ((g >> 1) & 1) * 8 + (lane & 7);
    const int bko  = (g & 1) * 8;

#pragma unroll
    for (int ks = 0; ks < 2; ks++) {
        const int kb = ks * 16;
        unsigned ar[4][4], br[4][2];
#pragma unroll
        for (int mf = 0; mf < 4; mf++) {
            int off = (wm * 64 + mf * 16 + lrow) * SRS + kb + lko;
            ldsm_x4(ar[mf][0], ar[mf][1], ar[mf][2], ar[mf][3], &S->A[off]);
        }
#pragma unroll
        for (int nfp = 0; nfp < 2; nfp++) {
            int off = (wn * 32 + nfp * 16 + bnr) * SRS + kb + bko;
            ldsm_x4(br[2 * nfp][0], br[2 * nfp][1],
                    br[2 * nfp + 1][0], br[2 * nfp + 1][1], &S->B[off]);
        }
#pragma unroll
        for (int mf = 0; mf < 4; mf++)
#pragma unroll
            for (int nf = 0; nf < 4; nf++)
                mma_f16(acc[mf][nf], ar[mf][0], ar[mf][1], ar[mf][2], ar[mf][3],
                        br[nf][0], br[nf][1]);
    }
}

__device__ __forceinline__ void gemm_mainloop(
    const __half* __restrict__ GA, const __half* __restrict__ GB,
    GemmSmem* SS, size_t t0, size_t o0, int tid,
    int wm, int wn, int lane, float acc[4][4][4])
{
    gemm_issue(GA, GB, &SS[0], t0, o0, 0, tid);
    asm volatile("cp.async.commit_group;" ::: "memory");
    gemm_issue(GA, GB, &SS[1], t0, o0, BK, tid);
    asm volatile("cp.async.commit_group;" ::: "memory");

#pragma unroll
    for (int kc = 0; kc < 8; kc++) {
        if (kc < 7)
            asm volatile("cp.async.wait_group 1;" ::: "memory");
        else
            asm volatile("cp.async.wait_group 0;" ::: "memory");
        __syncthreads();
        if (kc < 6) {
            gemm_issue(GA, GB, &SS[(kc + 2) % 3], t0, o0, (kc + 2) * BK, tid);
            asm volatile("cp.async.commit_group;" ::: "memory");
        }
        mma_chunk(&SS[kc % 3], wm, wn, lane, acc);
    }
}

// ---------------------------------------------------------------------------
// Kernel 1: QKV projection (fp16). Epilogue: Q fp16 pre-scaled, K fp16,
// V transposed fp16.
// ---------------------------------------------------------------------------
__global__ __launch_bounds__(256, 2) void qkv_gemm_kernel()
{
    extern __shared__ GemmSmem SS[];

    const int tid  = threadIdx.x;
    const int lane = tid & 31;
    const int warp = tid >> 5;
    const int gid  = lane >> 2;
    const int tig  = lane & 3;
    const int wm   = warp & 1;
    const int wn   = warp >> 1;
    const int t0   = blockIdx.x * 128;
    const int o0   = blockIdx.y * 128;

    float acc[4][4][4];
#pragma unroll
    for (int mf = 0; mf < 4; mf++)
#pragma unroll
        for (int nf = 0; nf < 4; nf++)
#pragma unroll
            for (int i = 0; i < 4; i++) acc[mf][nf][i] = 0.f;

    gemm_mainloop(g_xf, g_wqf, SS, t0, o0, tid, wm, wn, lane, acc);

    const int ocol0 = o0 + wn * 32;
    const int sel = ocol0 >> 8;
    const int h   = (ocol0 >> 5) & 7;

    if (sel < 2) {
        __half* dst = (sel == 0) ? g_qh : g_kh;
        float s = (sel == 0) ? SCALE_LOG2E : 1.f;
#pragma unroll
        for (int mf = 0; mf < 4; mf++) {
#pragma unroll
            for (int half = 0; half < 2; half++) {
                int t = t0 + wm * 64 + mf * 16 + gid + half * 8;
                int w = t / LW;
                int l = t - w * LW;
                size_t base = (size_t)((w * NH + h) * LW + l) * HD;
#pragma unroll
                for (int nf = 0; nf < 4; nf++) {
                    int d = nf * 8 + 2 * tig;
                    __half2 hv = __floats2half2_rn(
                        acc[mf][nf][half * 2] * s,
                        acc[mf][nf][half * 2 + 1] * s);
                    *(unsigned*)&dst[base + d] = *(unsigned*)&hv;
                }
            }
        }
    } else {
        // V: transposed fp16 store g_vt[(w*NH+h)*HD + d][l]
#pragma unroll
        for (int mf = 0; mf < 4; mf++) {
#pragma unroll
            for (int half = 0; half < 2; half++) {
                int t = t0 + wm * 64 + mf * 16 + gid + half * 8;
                int w = t / LW;
                int l = t - w * LW;
                size_t vb = (size_t)((w * NH + h) * HD) * LW + l;
#pragma unroll
                for (int nf = 0; nf < 4; nf++) {
                    int d = nf * 8 + 2 * tig;
                    g_vt[vb + (size_t)d * LW] =
                        __float2half_rn(acc[mf][nf][half * 2]);
                    g_vt[vb + (size_t)(d + 1) * LW] =
                        __float2half_rn(acc[mf][nf][half * 2 + 1]);
                }
            }
        }
    }
}

// ---------------------------------------------------------------------------
// Kernel 2: flash attention, all-fp16 mma, 3-stage cp.async pipeline,
// hoisted Q frags, ldmatrix K/V frags, f16x2 MUFU softmax + ones-mma sums.
// grid = (7, 256), block = 224 (7 warps), 3 CTAs/SM.
// ---------------------------------------------------------------------------
#define QKS 40
#define VTS 120
#define Q_HALVES  (112 * QKS)
#define K_HALVES  (112 * QKS)
#define V_HALVES  (HD * VTS)
#define ATTN_SMEM_BYTES ((Q_HALVES + 3 * K_HALVES + 3 * V_HALVES) * 2)

template<int NGN, int NGBASE>
__device__ __forceinline__ void attn_part(
    const unsigned qf[2][4], const __half* __restrict__ Ks,
    const __half* __restrict__ Vs, int lane,
    float oacc[4][4], float lsum[4])
{
    const int bnr = ((lane >> 4) & 1) * 8 + (lane & 7);
    const int bko = ((lane >> 3) & 1) * 8;
    const int vr  = lane & 7;
    const int vko = ((lane >> 3) & 1) * 8;

    float sacc[NGN][4];
#pragma unroll
    for (int ngl = 0; ngl < NGN; ngl++)
#pragma unroll
        for (int i = 0; i < 4; i++) sacc[ngl][i] = 0.f;

    // S = Q K^T ; K fragments via ldmatrix.x4
#pragma unroll
    for (int p = 0; p < NGN / 2; p++) {
#pragma unroll
        for (int ks = 0; ks < 2; ks++) {
            const __half* kb =
                &Ks[((NGBASE + 2 * p) * 8 + bnr) * QKS + ks * 16 + bko];
            unsigned b0, b1, b2, b3;
            ldsm_x4(b0, b1, b2, b3, kb);
            mma_f16(sacc[2 * p],     qf[ks][0], qf[ks][1], qf[ks][2],
                    qf[ks][3], b0, b1);
            mma_f16(sacc[2 * p + 1], qf[ks][0], qf[ks][1], qf[ks][2],
                    qf[ks][3], b2, b3);
        }
    }

    // cvt to fp16 pairs, ONE f16x2 MUFU exp each -> PV mma + ones-mma
#pragma unroll
    for (int ch = 0; ch < NGN / 2; ch++) {
        int ngl0 = 2 * ch, ngl1 = 2 * ch + 1;
        unsigned a0 = ex2_h2(__floats2half2_rn(sacc[ngl0][0], sacc[ngl0][1]));
        unsigned a1 = ex2_h2(__floats2half2_rn(sacc[ngl0][2], sacc[ngl0][3]));
        unsigned a2 = ex2_h2(__floats2half2_rn(sacc[ngl1][0], sacc[ngl1][1]));
        unsigned a3 = ex2_h2(__floats2half2_rn(sacc[ngl1][2], sacc[ngl1][3]));
        int kbase = (NGBASE / 2 + ch) * 16;
#pragma unroll
        for (int ng = 0; ng < 4; ng++) {
            const __half* vb = &Vs[(ng * 8 + vr) * VTS + kbase + vko];
            unsigned b0, b1;
            ldsm_x2(b0, b1, vb);
            mma_f16(oacc[ng], a0, a1, a2, a3, b0, b1);
        }
        mma_f16(lsum, a0, a1, a2, a3, ONES_H2, ONES_H2);
    }
}

__device__ __forceinline__ void attn_issue_tile(
    __half* Kd, __half* Vd, const __half* gkt, const __half* gvtt, int tid)
{
#pragma unroll
    for (int i2 = 0; i2 < 2; i2++) {
        int i = tid + i2 * 224;
        int r = i >> 2;
        int c = (i & 3) << 3;
        CP16((unsigned)__cvta_generic_to_shared(&Kd[r * QKS + c]),
             &gkt[r * 32 + c]);
    }
#pragma unroll
    for (int i2 = 0; i2 < 2; i2++) {
        int i = tid + i2 * 224;
        int d = i / 14;
        int c = i - d * 14;
        CP16((unsigned)__cvta_generic_to_shared(&Vd[d * VTS + c * 8]),
             &gvtt[(size_t)d * LW + c * 8]);
    }
    asm volatile("cp.async.commit_group;" ::: "memory");
}

__global__ __launch_bounds__(224, 3) void attn_kernel()
{
    extern __shared__ char smraw[];
    __half* Qs  = (__half*)smraw;
    __half* Ks0 = Qs + Q_HALVES;
    __half* Vs0 = Ks0 + 3 * K_HALVES;

    const int tid  = threadIdx.x;
    const int lane = tid & 31;
    const int warp = tid >> 5;
    const int gid  = lane >> 2;
    const int tig  = lane & 3;
    const int m0   = warp * 16;

    const int wh = blockIdx.y;
    const int q0 = blockIdx.x * 112;

    const __half* gq  = g_qh + (size_t)(wh * LW + q0) * HD;
    const __half* gk  = g_kh + (size_t)wh * LW * HD;
    const __half* gvt = g_vt + (size_t)wh * HD * LW;

    // group 0: Q + K/V tile 0
    {
#pragma unroll
        for (int i2 = 0; i2 < 2; i2++) {
            int i = tid + i2 * 224;
            int r = i >> 2;
            int c = (i & 3) << 3;
            CP16((unsigned)__cvta_generic_to_shared(&Qs[r * QKS + c]),
                 &gq[r * 32 + c]);
            CP16((unsigned)__cvta_generic_to_shared(&Ks0[r * QKS + c]),
                 &gk[r * 32 + c]);
        }
#pragma unroll
        for (int i2 = 0; i2 < 2; i2++) {
            int i = tid + i2 * 224;
            int d = i / 14;
            int c = i - d * 14;
            CP16((unsigned)__cvta_generic_to_shared(&Vs0[d * VTS + c * 8]),
                 &gvt[(size_t)d * LW + c * 8]);
        }
        asm volatile("cp.async.commit_group;" ::: "memory");
    }
    // group 1: K/V tile 1
    attn_issue_tile(Ks0 + K_HALVES, Vs0 + V_HALVES,
                    gk + 112 * 32, gvt + 112, tid);

    float oacc[4][4];
#pragma unroll
    for (int ng = 0; ng < 4; ng++)
#pragma unroll
        for (int i = 0; i < 4; i++) oacc[ng][i] = 0.f;
    float lsum[4] = {0.f, 0.f, 0.f, 0.f};
    unsigned qf[2][4];

    for (int kt = 0; kt < 7; kt++) {
        if (kt < 6)
            asm volatile("cp.async.wait_group 1;" ::: "memory");
        else
            asm volatile("cp.async.wait_group 0;" ::: "memory");
        __syncthreads();
        if (kt == 0) {
#pragma unroll
            for (int ks = 0; ks < 2; ks++) {
                const __half* qb = &Qs[(m0 + gid) * QKS + ks * 16 + 2 * tig];
                qf[ks][0] = *(const unsigned*)qb;
                qf[ks][1] = *(const unsigned*)(qb + 8 * QKS);
                qf[ks][2] = *(const unsigned*)(qb + 8);
                qf[ks][3] = *(const unsigned*)(qb + 8 * QKS + 8);
            }
        }
        if (kt < 5) {
            attn_issue_tile(Ks0 + ((kt + 2) % 3) * K_HALVES,
                            Vs0 + ((kt + 2) % 3) * V_HALVES,
                            gk + (kt + 2) * 112 * 32,
                            gvt + (kt + 2) * 112, tid);
        }

        const __half* Ks = Ks0 + (kt % 3) * K_HALVES;
        const __half* Vs = Vs0 + (kt % 3) * V_HALVES;

        attn_part<8, 0>(qf, Ks, Vs, lane, oacc, lsum);
        attn_part<6, 8>(qf, Ks, Vs, lane, oacc, lsum);
    }

    float inv0 = 1.f / lsum[0];
    float inv1 = 1.f / lsum[2];

    const int w = wh >> 3;
    const int h = wh & 7;
    const size_t tbase = (size_t)(w * LW + q0 + m0 + gid);
#pragma unroll
    for (int ng = 0; ng < 4; ng++) {
        int col = h * HD + ng * 8 + 2 * tig;
        __half2 hv0 = __floats2half2_rn(oacc[ng][0] * inv0,
                                        oacc[ng][1] * inv0);
        __half2 hv1 = __floats2half2_rn(oacc[ng][2] * inv1,
                                        oacc[ng][3] * inv1);
        *(unsigned*)&g_of[tbase * CDIM + col]       = *(unsigned*)&hv0;
        *(unsigned*)&g_of[(tbase + 8) * CDIM + col] = *(unsigned*)&hv1;
    }
}

// ---------------------------------------------------------------------------
// Kernel 3: output projection (fp16) + bias.
// ---------------------------------------------------------------------------
__global__ __launch_bounds__(256, 2) void proj_gemm_kernel(
    const float* __restrict__ bias, float* __restrict__ out)
{
    extern __shared__ GemmSmem SS[];

    const int tid  = threadIdx.x;
    const int lane = tid & 31;
    const int warp = tid >> 5;
    const int gid  = lane >> 2;
    const int tig  = lane & 3;
    const int wm   = warp & 1;
    const int wn   = warp >> 1;
    const int t0   = blockIdx.x * 128;
    const int o0   = blockIdx.y * 128;

    float acc[4][4][4];
#pragma unroll
    for (int mf = 0; mf < 4; mf++)
#pragma unroll
        for (int nf = 0; nf < 4; nf++)
#pragma unroll
            for (int i = 0; i < 4; i++) acc[mf][nf][i] = 0.f;

    gemm_mainloop(g_of, g_wpf, SS, t0, o0, tid, wm, wn, lane, acc);

    const int ocol0 = o0 + wn * 32;
#pragma unroll
    for (int mf = 0; mf < 4; mf++) {
#pragma unroll
        for (int half = 0; half < 2; half++) {
            int t = t0 + wm * 64 + mf * 16 + gid + half * 8;
#pragma unroll
            for (int nf = 0; nf < 4; nf++) {
                int o = ocol0 + nf * 8 + 2 * tig;
                float2 bv = *(const float2*)&bias[o];
                *(float2*)&out[(size_t)t * CDIM + o] = make_float2(
                    acc[mf][nf][half * 2] + bv.x,
                    acc[mf][nf][half * 2 + 1] + bv.y);
            }
        }
    }
}

// ---------------------------------------------------------------------------
extern "C" void kernel_launch(void* const* d_in, const int* in_sizes, int n_in,
                              void* d_out, int out_size)
{
    const float* x      = (const float*)d_in[0];
    const float* qkv_w  = (const float*)d_in[1];
    const float* proj_w = (const float*)d_in[2];
    const float* proj_b = (const float*)d_in[3];
    float* out = (float*)d_out;

    cudaFuncSetAttribute(qkv_gemm_kernel,
                         cudaFuncAttributeMaxDynamicSharedMemorySize,
                         GEMM_SMEM_BYTES);
    cudaFuncSetAttribute(proj_gemm_kernel,
                         cudaFuncAttributeMaxDynamicSharedMemorySize,
                         GEMM_SMEM_BYTES);
    cudaFuncSetAttribute(attn_kernel,
                         cudaFuncAttributeMaxDynamicSharedMemorySize,
                         ATTN_SMEM_BYTES);

    conv_all_kernel<<<XB + WQB + WPB, 256>>>(x, qkv_w, proj_w);
    qkv_gemm_kernel<<<dim3(TTOK / 128, 768 / 128), 256, GEMM_SMEM_BYTES>>>();
    attn_kernel<<<dim3(LW / 112, NWIN * NH), 224, ATTN_SMEM_BYTES>>>();
    proj_gemm_kernel<<<dim3(TTOK / 128, CDIM / 128), 256, GEMM_SMEM_BYTES>>>(proj_b, out);
}